// round 5
// baseline (speedup 1.0000x reference)
#include <cuda_runtime.h>

// Problem constants
constexpr int Bb = 8, Tt = 1024, Dd = 512, Hh = 8, KDk = 64;
constexpr int BT = Bb * Tt;          // 8192
constexpr int HD = Hh * KDk;         // 512
constexpr int OUT_ELEMS = Bb * Tt * Dd;  // 4194304 (offset of attn_weights in d_out)

// Scratch (allocation-free: device globals). 16B alignment for float4 access.
__device__ __align__(16) float g_qh[BT * HD];
__device__ __align__(16) float g_kh[BT * HD];
__device__ __align__(16) float g_vh[BT * HD];
__device__ __align__(16) float g_att[BT * HD];

// ---------------------------------------------------------------------------
// Generic fp32 GEMM: C[M,N] = A[M,K] @ B[K,N], all row-major.
// 128x128 tile, BK=16, 256 threads, 8x8 micro-tile in split 4+4 layout.
// All smem row strides are multiples of 4 floats (16B) for LDS.128.
// ---------------------------------------------------------------------------
__global__ __launch_bounds__(256, 2)
void sgemm_128x128(const float* __restrict__ A, const float* __restrict__ B,
                   float* __restrict__ C, int M, int N, int K)
{
    __shared__ float As[16][132];   // K-major: As[k][m]  (132*4=528B, 16B-mult)
    __shared__ float Bs[16][132];   // K-major: Bs[k][n]

    const int tid = threadIdx.x;
    const int tx = tid & 15, ty = tid >> 4;
    const int row0 = blockIdx.y * 128;
    const int col0 = blockIdx.x * 128;

    const int arow = tid >> 2;         // 0..63
    const int acol = (tid & 3) << 2;   // 0,4,8,12
    const int brow = tid >> 5;         // 0..7
    const int bcol = (tid & 31) << 2;  // 0..124

    float acc[8][8];
#pragma unroll
    for (int i = 0; i < 8; i++)
#pragma unroll
        for (int j = 0; j < 8; j++) acc[i][j] = 0.f;

    for (int k0 = 0; k0 < K; k0 += 16) {
        float4 a0 = *(const float4*)(A + (size_t)(row0 + arow) * K + k0 + acol);
        float4 a1 = *(const float4*)(A + (size_t)(row0 + arow + 64) * K + k0 + acol);
        float4 b0 = *(const float4*)(B + (size_t)(k0 + brow) * N + col0 + bcol);
        float4 b1 = *(const float4*)(B + (size_t)(k0 + brow + 8) * N + col0 + bcol);
        __syncthreads();
        As[acol + 0][arow] = a0.x; As[acol + 1][arow] = a0.y;
        As[acol + 2][arow] = a0.z; As[acol + 3][arow] = a0.w;
        As[acol + 0][arow + 64] = a1.x; As[acol + 1][arow + 64] = a1.y;
        As[acol + 2][arow + 64] = a1.z; As[acol + 3][arow + 64] = a1.w;
        *(float4*)&Bs[brow][bcol]     = b0;
        *(float4*)&Bs[brow + 8][bcol] = b1;
        __syncthreads();
#pragma unroll
        for (int kk = 0; kk < 16; kk++) {
            float ra[8], rb[8];
            *(float4*)(ra)     = *(const float4*)&As[kk][ty * 4];
            *(float4*)(ra + 4) = *(const float4*)&As[kk][64 + ty * 4];
            *(float4*)(rb)     = *(const float4*)&Bs[kk][tx * 4];
            *(float4*)(rb + 4) = *(const float4*)&Bs[kk][64 + tx * 4];
#pragma unroll
            for (int i = 0; i < 8; i++)
#pragma unroll
                for (int j = 0; j < 8; j++)
                    acc[i][j] = fmaf(ra[i], rb[j], acc[i][j]);
        }
    }

#pragma unroll
    for (int i = 0; i < 8; i++) {
        const int r = row0 + ((i < 4) ? (ty * 4 + i) : (64 + ty * 4 + (i - 4)));
        float* cp = C + (size_t)r * N + col0;
        *(float4*)(cp + tx * 4)      = make_float4(acc[i][0], acc[i][1], acc[i][2], acc[i][3]);
        *(float4*)(cp + 64 + tx * 4) = make_float4(acc[i][4], acc[i][5], acc[i][6], acc[i][7]);
    }
}

// ---------------------------------------------------------------------------
// RBF weights: for one (b,h), one 128x128 tile of W = exp(2*QK^T - |q|^2 - |k|^2)
// Q,K tiles are 128x64; contraction split into two kk-chunks of 32.
// Padding 132 (528B rows) keeps LDS.128 16B-aligned (130 was the crash).
// ---------------------------------------------------------------------------
__global__ __launch_bounds__(256, 2)
void rbf_weights(const float* __restrict__ qh, const float* __restrict__ kh,
                 float* __restrict__ W)
{
    __shared__ float Qs[32][132];   // [kk][row]
    __shared__ float Ks[32][132];   // [kk][col]
    __shared__ float q2s[128], k2s[128];

    const int tid = threadIdx.x;
    const int tx = tid & 15, ty = tid >> 4;
    const int kt = blockIdx.x, qt = blockIdx.y, bh = blockIdx.z;
    const int b = bh >> 3, h = bh & 7;

    const float* qbase = qh + (size_t)(b * Tt + qt * 128) * HD + h * 64;
    const float* kbase = kh + (size_t)(b * Tt + kt * 128) * HD + h * 64;

    if (tid < 128) { q2s[tid] = 0.f; k2s[tid] = 0.f; }

    const int lc  = (tid & 7) << 2;  // kk float4 col: 0..28
    const int lr0 = tid >> 3;        // 0..31

    float acc[8][8];
#pragma unroll
    for (int i = 0; i < 8; i++)
#pragma unroll
        for (int j = 0; j < 8; j++) acc[i][j] = 0.f;

    for (int c = 0; c < 2; c++) {
        __syncthreads();
#pragma unroll
        for (int rr = 0; rr < 128; rr += 32) {
            const int r = lr0 + rr;
            float4 a = *(const float4*)(qbase + (size_t)r * HD + c * 32 + lc);
            Qs[lc + 0][r] = a.x; Qs[lc + 1][r] = a.y;
            Qs[lc + 2][r] = a.z; Qs[lc + 3][r] = a.w;
            float4 e = *(const float4*)(kbase + (size_t)r * HD + c * 32 + lc);
            Ks[lc + 0][r] = e.x; Ks[lc + 1][r] = e.y;
            Ks[lc + 2][r] = e.z; Ks[lc + 3][r] = e.w;
        }
        __syncthreads();
        // Row norms (128 threads each for q and k)
        if (tid < 128) {
            float s = 0.f;
#pragma unroll
            for (int kk = 0; kk < 32; kk++) { float v = Qs[kk][tid]; s = fmaf(v, v, s); }
            q2s[tid] += s;
        } else {
            const int j = tid - 128;
            float s = 0.f;
#pragma unroll
            for (int kk = 0; kk < 32; kk++) { float v = Ks[kk][j]; s = fmaf(v, v, s); }
            k2s[j] += s;
        }
        // S accumulation
#pragma unroll
        for (int kk = 0; kk < 32; kk++) {
            float ra[8], rb[8];
            *(float4*)(ra)     = *(const float4*)&Qs[kk][ty * 4];
            *(float4*)(ra + 4) = *(const float4*)&Qs[kk][64 + ty * 4];
            *(float4*)(rb)     = *(const float4*)&Ks[kk][tx * 4];
            *(float4*)(rb + 4) = *(const float4*)&Ks[kk][64 + tx * 4];
#pragma unroll
            for (int i = 0; i < 8; i++)
#pragma unroll
                for (int j = 0; j < 8; j++)
                    acc[i][j] = fmaf(ra[i], rb[j], acc[i][j]);
        }
    }
    __syncthreads();

    float rq2[8], rk2[8];
#pragma unroll
    for (int i = 0; i < 8; i++)
        rq2[i] = q2s[(i < 4) ? (ty * 4 + i) : (64 + ty * 4 + (i - 4))];
#pragma unroll
    for (int j = 0; j < 8; j++)
        rk2[j] = k2s[(j < 4) ? (tx * 4 + j) : (64 + tx * 4 + (j - 4))];

    float* wb = W + ((size_t)bh * Tt + qt * 128) * Tt + kt * 128;
#pragma unroll
    for (int i = 0; i < 8; i++) {
        const int r = (i < 4) ? (ty * 4 + i) : (64 + ty * 4 + (i - 4));
        float4 v0, v1;
        v0.x = __expf(2.f * acc[i][0] - rq2[i] - rk2[0]);
        v0.y = __expf(2.f * acc[i][1] - rq2[i] - rk2[1]);
        v0.z = __expf(2.f * acc[i][2] - rq2[i] - rk2[2]);
        v0.w = __expf(2.f * acc[i][3] - rq2[i] - rk2[3]);
        v1.x = __expf(2.f * acc[i][4] - rq2[i] - rk2[4]);
        v1.y = __expf(2.f * acc[i][5] - rq2[i] - rk2[5]);
        v1.z = __expf(2.f * acc[i][6] - rq2[i] - rk2[6]);
        v1.w = __expf(2.f * acc[i][7] - rq2[i] - rk2[7]);
        *(float4*)(wb + (size_t)r * Tt + tx * 4)      = v0;
        *(float4*)(wb + (size_t)r * Tt + 64 + tx * 4) = v1;
    }
}

// ---------------------------------------------------------------------------
// attn = W @ V per (b,h): M=1024(t), N=64(d), K=1024(Tk). BM=128, BN=64, BK=32.
// 256 threads, 8x4 micro per thread (rows split 4+4).
// ---------------------------------------------------------------------------
__global__ __launch_bounds__(256, 2)
void wv_gemm(const float* __restrict__ W, const float* __restrict__ vh,
             float* __restrict__ att)
{
    __shared__ float Ws[32][132];   // [j][row]  (528B rows)
    __shared__ float Vs[32][68];    // [j][d]    (272B rows, 16B-mult)

    const int tid = threadIdx.x;
    const int tx = tid & 15, ty = tid >> 4;
    const int qt = blockIdx.x, bh = blockIdx.y;
    const int b = bh >> 3, h = bh & 7;

    const float* wbase = W + ((size_t)bh * Tt + qt * 128) * Tt;
    const float* vbase = vh + (size_t)(b * Tt) * HD + h * 64;

    float acc[8][4];
#pragma unroll
    for (int i = 0; i < 8; i++)
#pragma unroll
        for (int j = 0; j < 4; j++) acc[i][j] = 0.f;

    const int wc  = (tid & 7) << 2;   // 0..28
    const int wr0 = tid >> 3;         // 0..31
    const int vc  = (tid & 15) << 2;  // 0..60
    const int vr0 = tid >> 4;         // 0..15

    for (int k0 = 0; k0 < Tt; k0 += 32) {
        __syncthreads();
#pragma unroll
        for (int rr = 0; rr < 128; rr += 32) {
            const int r = wr0 + rr;
            float4 a = *(const float4*)(wbase + (size_t)r * Tt + k0 + wc);
            Ws[wc + 0][r] = a.x; Ws[wc + 1][r] = a.y;
            Ws[wc + 2][r] = a.z; Ws[wc + 3][r] = a.w;
        }
#pragma unroll
        for (int rr = 0; rr < 32; rr += 16) {
            const int r = vr0 + rr;
            *(float4*)&Vs[r][vc] = *(const float4*)(vbase + (size_t)(k0 + r) * HD + vc);
        }
        __syncthreads();
#pragma unroll
        for (int j = 0; j < 32; j++) {
            float ra[8], rb[4];
            *(float4*)(ra)     = *(const float4*)&Ws[j][ty * 4];
            *(float4*)(ra + 4) = *(const float4*)&Ws[j][64 + ty * 4];
            *(float4*)(rb)     = *(const float4*)&Vs[j][tx * 4];
#pragma unroll
            for (int i = 0; i < 8; i++)
#pragma unroll
                for (int jj = 0; jj < 4; jj++)
                    acc[i][jj] = fmaf(ra[i], rb[jj], acc[i][jj]);
        }
    }

    float* ob = att + (size_t)(b * Tt + qt * 128) * HD + h * 64;
#pragma unroll
    for (int i = 0; i < 8; i++) {
        const int r = (i < 4) ? (ty * 4 + i) : (64 + ty * 4 + (i - 4));
        *(float4*)(ob + (size_t)r * HD + tx * 4) =
            make_float4(acc[i][0], acc[i][1], acc[i][2], acc[i][3]);
    }
}

// ---------------------------------------------------------------------------
extern "C" void kernel_launch(void* const* d_in, const int* in_sizes, int n_in,
                              void* d_out, int out_size)
{
    (void)in_sizes; (void)n_in; (void)out_size;

    const float* q  = (const float*)d_in[0];
    const float* k  = (const float*)d_in[1];
    const float* v  = (const float*)d_in[2];
    const float* Wq = (const float*)d_in[3];
    const float* Wk = (const float*)d_in[4];
    const float* Wv = (const float*)d_in[5];
    const float* Wo = (const float*)d_in[6];

    float* out = (float*)d_out;             // [B,T,D]
    float* wts = out + OUT_ELEMS;           // [B,H,T,T]

    void *pq, *pk, *pv, *pa;
    cudaGetSymbolAddress(&pq, g_qh);
    cudaGetSymbolAddress(&pk, g_kh);
    cudaGetSymbolAddress(&pv, g_vh);
    cudaGetSymbolAddress(&pa, g_att);
    float* qh  = (float*)pq;
    float* kh  = (float*)pk;
    float* vh  = (float*)pv;
    float* att = (float*)pa;

    dim3 blk(256);
    // Projections
    sgemm_128x128<<<dim3(HD / 128, BT / 128), blk>>>(q, Wq, qh, BT, HD, Dd);
    sgemm_128x128<<<dim3(HD / 128, BT / 128), blk>>>(k, Wk, kh, BT, HD, Dd);
    sgemm_128x128<<<dim3(HD / 128, BT / 128), blk>>>(v, Wv, vh, BT, HD, Dd);
    // Attention weights (writes the attn_weights output region)
    rbf_weights<<<dim3(Tt / 128, Tt / 128, Bb * Hh), blk>>>(qh, kh, wts);
    // attn = W @ V
    wv_gemm<<<dim3(Tt / 128, Bb * Hh), blk>>>(wts, vh, att);
    // out = attn @ Wo
    sgemm_128x128<<<dim3(Dd / 128, BT / 128), blk>>>(att, Wo, out, BT, Dd, HD);
}

// round 6
// speedup vs baseline: 1.1023x; 1.1023x over previous
#include <cuda_runtime.h>

// Problem constants
constexpr int Bb = 8, Tt = 1024, Dd = 512, Hh = 8, KDk = 64;
constexpr int BT = Bb * Tt;          // 8192
constexpr int HD = Hh * KDk;         // 512
constexpr int OUT_ELEMS = Bb * Tt * Dd;  // offset of attn_weights in d_out

// Scratch (allocation-free: device globals). 16B alignment for float4 access.
__device__ __align__(16) float g_qh[BT * HD];
__device__ __align__(16) float g_kh[BT * HD];
__device__ __align__(16) float g_vh[BT * HD];
__device__ __align__(16) float g_att[BT * HD];

// ---------------------------------------------------------------------------
// Core fp32 GEMM: C[8192,512] = A[8192,512] @ B[512,512], row-major.
// 128x128 tile, BK=16, 256 threads, 8x8 micro (split 4+4), double-buffered
// smem with a single __syncthreads per k-step.
// ---------------------------------------------------------------------------
struct SmemGemm {
    float As[2][16][132];   // K-major: As[buf][k][m]  (528B rows, 16B-mult)
    float Bs[2][16][132];   // K-major: Bs[buf][k][n]
};

__device__ __forceinline__ void gemm_core(const float* __restrict__ A,
                                          const float* __restrict__ B,
                                          float* __restrict__ C,
                                          SmemGemm& s)
{
    constexpr int K = 512, N = 512;
    const int tid = threadIdx.x;
    const int tx = tid & 15, ty = tid >> 4;
    const int row0 = blockIdx.y * 128, col0 = blockIdx.x * 128;
    const int arow = tid >> 2;         // 0..63
    const int acol = (tid & 3) << 2;   // 0,4,8,12
    const int brow = tid >> 5;         // 0..7
    const int bcol = (tid & 31) << 2;  // 0..124

    const float* Ap0 = A + (size_t)(row0 + arow) * K + acol;
    const float* Ap1 = Ap0 + (size_t)64 * K;
    const float* Bp0 = B + (size_t)brow * N + col0 + bcol;
    const float* Bp1 = Bp0 + (size_t)8 * N;

    float acc[8][8];
#pragma unroll
    for (int i = 0; i < 8; i++)
#pragma unroll
        for (int j = 0; j < 8; j++) acc[i][j] = 0.f;

    auto step = [&](int bsel) {
#pragma unroll
        for (int kk = 0; kk < 16; kk++) {
            float ra[8], rb[8];
            *(float4*)(ra)     = *(const float4*)&s.As[bsel][kk][ty * 4];
            *(float4*)(ra + 4) = *(const float4*)&s.As[bsel][kk][64 + ty * 4];
            *(float4*)(rb)     = *(const float4*)&s.Bs[bsel][kk][tx * 4];
            *(float4*)(rb + 4) = *(const float4*)&s.Bs[bsel][kk][64 + tx * 4];
#pragma unroll
            for (int i = 0; i < 8; i++)
#pragma unroll
                for (int j = 0; j < 8; j++)
                    acc[i][j] = fmaf(ra[i], rb[j], acc[i][j]);
        }
    };

    // Prefetch tile 0 -> buf 0
    float4 a0 = *(const float4*)Ap0;
    float4 a1 = *(const float4*)Ap1;
    float4 b0 = *(const float4*)Bp0;
    float4 b1 = *(const float4*)Bp1;
    s.As[0][acol + 0][arow] = a0.x; s.As[0][acol + 1][arow] = a0.y;
    s.As[0][acol + 2][arow] = a0.z; s.As[0][acol + 3][arow] = a0.w;
    s.As[0][acol + 0][arow + 64] = a1.x; s.As[0][acol + 1][arow + 64] = a1.y;
    s.As[0][acol + 2][arow + 64] = a1.z; s.As[0][acol + 3][arow + 64] = a1.w;
    *(float4*)&s.Bs[0][brow][bcol]     = b0;
    *(float4*)&s.Bs[0][brow + 8][bcol] = b1;
    __syncthreads();

    int buf = 0;
    for (int k0 = 16; k0 < K; k0 += 16) {
        a0 = *(const float4*)(Ap0 + k0);
        a1 = *(const float4*)(Ap1 + k0);
        b0 = *(const float4*)(Bp0 + (size_t)k0 * N);
        b1 = *(const float4*)(Bp1 + (size_t)k0 * N);

        step(buf);

        const int nb = buf ^ 1;
        s.As[nb][acol + 0][arow] = a0.x; s.As[nb][acol + 1][arow] = a0.y;
        s.As[nb][acol + 2][arow] = a0.z; s.As[nb][acol + 3][arow] = a0.w;
        s.As[nb][acol + 0][arow + 64] = a1.x; s.As[nb][acol + 1][arow + 64] = a1.y;
        s.As[nb][acol + 2][arow + 64] = a1.z; s.As[nb][acol + 3][arow + 64] = a1.w;
        *(float4*)&s.Bs[nb][brow][bcol]     = b0;
        *(float4*)&s.Bs[nb][brow + 8][bcol] = b1;
        __syncthreads();
        buf = nb;
    }
    step(buf);

#pragma unroll
    for (int i = 0; i < 8; i++) {
        const int r = row0 + ((i < 4) ? (ty * 4 + i) : (64 + ty * 4 + (i - 4)));
        float* cp = C + (size_t)r * N + col0;
        *(float4*)(cp + tx * 4)      = make_float4(acc[i][0], acc[i][1], acc[i][2], acc[i][3]);
        *(float4*)(cp + 64 + tx * 4) = make_float4(acc[i][4], acc[i][5], acc[i][6], acc[i][7]);
    }
}

// All three projections in one launch (grid.z selects which) — fills the chip.
__global__ __launch_bounds__(256, 2)
void proj3_kernel(const float* __restrict__ q, const float* __restrict__ k,
                  const float* __restrict__ v,
                  const float* __restrict__ Wq, const float* __restrict__ Wk,
                  const float* __restrict__ Wv,
                  float* __restrict__ qh, float* __restrict__ kh,
                  float* __restrict__ vh)
{
    __shared__ SmemGemm s;
    const float* A; const float* Bm; float* C;
    if (blockIdx.z == 0)      { A = q; Bm = Wq; C = qh; }
    else if (blockIdx.z == 1) { A = k; Bm = Wk; C = kh; }
    else                      { A = v; Bm = Wv; C = vh; }
    gemm_core(A, Bm, C, s);
}

__global__ __launch_bounds__(256, 2)
void outproj_kernel(const float* __restrict__ att, const float* __restrict__ Wo,
                    float* __restrict__ out)
{
    __shared__ SmemGemm s;
    gemm_core(att, Wo, out, s);
}

// ---------------------------------------------------------------------------
// RBF weights: one 128x128 tile of W = exp(2*QK^T - |q|^2 - |k|^2) per block.
// Contraction over KD=64 in 4 chunks of 16, double-buffered; row norms
// accumulated per chunk from smem.
// ---------------------------------------------------------------------------
__global__ __launch_bounds__(256, 2)
void rbf_weights(const float* __restrict__ qh, const float* __restrict__ kh,
                 float* __restrict__ W)
{
    __shared__ float Qs[2][16][132];   // [buf][kk][row]
    __shared__ float Ks[2][16][132];   // [buf][kk][col]
    __shared__ float q2s[128], k2s[128];

    const int tid = threadIdx.x;
    const int tx = tid & 15, ty = tid >> 4;
    const int kt = blockIdx.x, qt = blockIdx.y, bh = blockIdx.z;
    const int b = bh >> 3, h = bh & 7;

    const float* qbase = qh + (size_t)(b * Tt + qt * 128) * HD + h * 64;
    const float* kbase = kh + (size_t)(b * Tt + kt * 128) * HD + h * 64;

    const int lr = tid >> 2;           // 0..63
    const int lc = (tid & 3) << 2;     // 0,4,8,12

    if (tid < 128) { q2s[tid] = 0.f; k2s[tid] = 0.f; }

    float acc[8][8];
#pragma unroll
    for (int i = 0; i < 8; i++)
#pragma unroll
        for (int j = 0; j < 8; j++) acc[i][j] = 0.f;

    auto norms = [&](int bsel) {
        if (tid < 128) {
            float sm = 0.f;
#pragma unroll
            for (int kk = 0; kk < 16; kk++) { float vv = Qs[bsel][kk][tid]; sm = fmaf(vv, vv, sm); }
            q2s[tid] += sm;
        } else {
            const int j = tid - 128;
            float sm = 0.f;
#pragma unroll
            for (int kk = 0; kk < 16; kk++) { float vv = Ks[bsel][kk][j]; sm = fmaf(vv, vv, sm); }
            k2s[j] += sm;
        }
    };
    auto step = [&](int bsel) {
#pragma unroll
        for (int kk = 0; kk < 16; kk++) {
            float ra[8], rb[8];
            *(float4*)(ra)     = *(const float4*)&Qs[bsel][kk][ty * 4];
            *(float4*)(ra + 4) = *(const float4*)&Qs[bsel][kk][64 + ty * 4];
            *(float4*)(rb)     = *(const float4*)&Ks[bsel][kk][tx * 4];
            *(float4*)(rb + 4) = *(const float4*)&Ks[bsel][kk][64 + tx * 4];
#pragma unroll
            for (int i = 0; i < 8; i++)
#pragma unroll
                for (int j = 0; j < 8; j++)
                    acc[i][j] = fmaf(ra[i], rb[j], acc[i][j]);
        }
    };

    // Prefetch chunk 0 -> buf 0
    float4 qa0 = *(const float4*)(qbase + (size_t)lr * HD + lc);
    float4 qa1 = *(const float4*)(qbase + (size_t)(lr + 64) * HD + lc);
    float4 ka0 = *(const float4*)(kbase + (size_t)lr * HD + lc);
    float4 ka1 = *(const float4*)(kbase + (size_t)(lr + 64) * HD + lc);
    Qs[0][lc + 0][lr] = qa0.x; Qs[0][lc + 1][lr] = qa0.y;
    Qs[0][lc + 2][lr] = qa0.z; Qs[0][lc + 3][lr] = qa0.w;
    Qs[0][lc + 0][lr + 64] = qa1.x; Qs[0][lc + 1][lr + 64] = qa1.y;
    Qs[0][lc + 2][lr + 64] = qa1.z; Qs[0][lc + 3][lr + 64] = qa1.w;
    Ks[0][lc + 0][lr] = ka0.x; Ks[0][lc + 1][lr] = ka0.y;
    Ks[0][lc + 2][lr] = ka0.z; Ks[0][lc + 3][lr] = ka0.w;
    Ks[0][lc + 0][lr + 64] = ka1.x; Ks[0][lc + 1][lr + 64] = ka1.y;
    Ks[0][lc + 2][lr + 64] = ka1.z; Ks[0][lc + 3][lr + 64] = ka1.w;
    __syncthreads();

    int buf = 0;
    for (int c = 1; c < 4; c++) {
        const int off = c * 16 + lc;
        qa0 = *(const float4*)(qbase + (size_t)lr * HD + off);
        qa1 = *(const float4*)(qbase + (size_t)(lr + 64) * HD + off);
        ka0 = *(const float4*)(kbase + (size_t)lr * HD + off);
        ka1 = *(const float4*)(kbase + (size_t)(lr + 64) * HD + off);

        norms(buf);
        step(buf);

        const int nb = buf ^ 1;
        Qs[nb][lc + 0][lr] = qa0.x; Qs[nb][lc + 1][lr] = qa0.y;
        Qs[nb][lc + 2][lr] = qa0.z; Qs[nb][lc + 3][lr] = qa0.w;
        Qs[nb][lc + 0][lr + 64] = qa1.x; Qs[nb][lc + 1][lr + 64] = qa1.y;
        Qs[nb][lc + 2][lr + 64] = qa1.z; Qs[nb][lc + 3][lr + 64] = qa1.w;
        Ks[nb][lc + 0][lr] = ka0.x; Ks[nb][lc + 1][lr] = ka0.y;
        Ks[nb][lc + 2][lr] = ka0.z; Ks[nb][lc + 3][lr] = ka0.w;
        Ks[nb][lc + 0][lr + 64] = ka1.x; Ks[nb][lc + 1][lr + 64] = ka1.y;
        Ks[nb][lc + 2][lr + 64] = ka1.z; Ks[nb][lc + 3][lr + 64] = ka1.w;
        __syncthreads();
        buf = nb;
    }
    norms(buf);
    step(buf);
    __syncthreads();   // q2s/k2s complete before cross-thread reads

    float rq2[8], rk2[8];
#pragma unroll
    for (int i = 0; i < 8; i++)
        rq2[i] = q2s[(i < 4) ? (ty * 4 + i) : (64 + ty * 4 + (i - 4))];
#pragma unroll
    for (int j = 0; j < 8; j++)
        rk2[j] = k2s[(j < 4) ? (tx * 4 + j) : (64 + tx * 4 + (j - 4))];

    float* wb = W + ((size_t)bh * Tt + qt * 128) * Tt + kt * 128;
#pragma unroll
    for (int i = 0; i < 8; i++) {
        const int r = (i < 4) ? (ty * 4 + i) : (64 + ty * 4 + (i - 4));
        float4 v0, v1;
        v0.x = __expf(2.f * acc[i][0] - rq2[i] - rk2[0]);
        v0.y = __expf(2.f * acc[i][1] - rq2[i] - rk2[1]);
        v0.z = __expf(2.f * acc[i][2] - rq2[i] - rk2[2]);
        v0.w = __expf(2.f * acc[i][3] - rq2[i] - rk2[3]);
        v1.x = __expf(2.f * acc[i][4] - rq2[i] - rk2[4]);
        v1.y = __expf(2.f * acc[i][5] - rq2[i] - rk2[5]);
        v1.z = __expf(2.f * acc[i][6] - rq2[i] - rk2[6]);
        v1.w = __expf(2.f * acc[i][7] - rq2[i] - rk2[7]);
        *(float4*)(wb + (size_t)r * Tt + tx * 4)      = v0;
        *(float4*)(wb + (size_t)r * Tt + 64 + tx * 4) = v1;
    }
}

// ---------------------------------------------------------------------------
// attn = W @ V per (b,h): M=1024, N=64, K=1024. BM=128, BN=64, BK=16,
// double-buffered, 256 threads, 8x4 micro (rows split 4+4).
// ---------------------------------------------------------------------------
__global__ __launch_bounds__(256, 2)
void wv_gemm(const float* __restrict__ W, const float* __restrict__ vh,
             float* __restrict__ att)
{
    __shared__ float Ws[2][16][132];   // [buf][j][row]
    __shared__ float Vs[2][16][68];    // [buf][j][d]

    const int tid = threadIdx.x;
    const int tx = tid & 15, ty = tid >> 4;
    const int qt = blockIdx.x, bh = blockIdx.y;
    const int b = bh >> 3, h = bh & 7;

    const float* wbase = W + ((size_t)bh * Tt + qt * 128) * Tt;
    const float* vbase = vh + (size_t)(b * Tt) * HD + h * 64;

    const int wr = tid >> 2;           // 0..63
    const int wc = (tid & 3) << 2;     // 0,4,8,12
    const int vr = tid >> 4;           // 0..15
    const int vc = (tid & 15) << 2;    // 0..60

    float acc[8][4];
#pragma unroll
    for (int i = 0; i < 8; i++)
#pragma unroll
        for (int j = 0; j < 4; j++) acc[i][j] = 0.f;

    auto step = [&](int bsel) {
#pragma unroll
        for (int j = 0; j < 16; j++) {
            float ra[8], rb[4];
            *(float4*)(ra)     = *(const float4*)&Ws[bsel][j][ty * 4];
            *(float4*)(ra + 4) = *(const float4*)&Ws[bsel][j][64 + ty * 4];
            *(float4*)(rb)     = *(const float4*)&Vs[bsel][j][tx * 4];
#pragma unroll
            for (int i = 0; i < 8; i++)
#pragma unroll
                for (int jj = 0; jj < 4; jj++)
                    acc[i][jj] = fmaf(ra[i], rb[jj], acc[i][jj]);
        }
    };

    // Prefetch k0 = 0 -> buf 0
    float4 w0 = *(const float4*)(wbase + (size_t)wr * Tt + wc);
    float4 w1 = *(const float4*)(wbase + (size_t)(wr + 64) * Tt + wc);
    float4 vv = *(const float4*)(vbase + (size_t)vr * HD + vc);
    Ws[0][wc + 0][wr] = w0.x; Ws[0][wc + 1][wr] = w0.y;
    Ws[0][wc + 2][wr] = w0.z; Ws[0][wc + 3][wr] = w0.w;
    Ws[0][wc + 0][wr + 64] = w1.x; Ws[0][wc + 1][wr + 64] = w1.y;
    Ws[0][wc + 2][wr + 64] = w1.z; Ws[0][wc + 3][wr + 64] = w1.w;
    *(float4*)&Vs[0][vr][vc] = vv;
    __syncthreads();

    int buf = 0;
    for (int k0 = 16; k0 < Tt; k0 += 16) {
        w0 = *(const float4*)(wbase + (size_t)wr * Tt + k0 + wc);
        w1 = *(const float4*)(wbase + (size_t)(wr + 64) * Tt + k0 + wc);
        vv = *(const float4*)(vbase + (size_t)(k0 + vr) * HD + vc);

        step(buf);

        const int nb = buf ^ 1;
        Ws[nb][wc + 0][wr] = w0.x; Ws[nb][wc + 1][wr] = w0.y;
        Ws[nb][wc + 2][wr] = w0.z; Ws[nb][wc + 3][wr] = w0.w;
        Ws[nb][wc + 0][wr + 64] = w1.x; Ws[nb][wc + 1][wr + 64] = w1.y;
        Ws[nb][wc + 2][wr + 64] = w1.z; Ws[nb][wc + 3][wr + 64] = w1.w;
        *(float4*)&Vs[nb][vr][vc] = vv;
        __syncthreads();
        buf = nb;
    }
    step(buf);

    float* ob = att + (size_t)(b * Tt + qt * 128) * HD + h * 64;
#pragma unroll
    for (int i = 0; i < 8; i++) {
        const int r = (i < 4) ? (ty * 4 + i) : (64 + ty * 4 + (i - 4));
        *(float4*)(ob + (size_t)r * HD + tx * 4) =
            make_float4(acc[i][0], acc[i][1], acc[i][2], acc[i][3]);
    }
}

// ---------------------------------------------------------------------------
extern "C" void kernel_launch(void* const* d_in, const int* in_sizes, int n_in,
                              void* d_out, int out_size)
{
    (void)in_sizes; (void)n_in; (void)out_size;

    const float* q  = (const float*)d_in[0];
    const float* k  = (const float*)d_in[1];
    const float* v  = (const float*)d_in[2];
    const float* Wq = (const float*)d_in[3];
    const float* Wk = (const float*)d_in[4];
    const float* Wv = (const float*)d_in[5];
    const float* Wo = (const float*)d_in[6];

    float* out = (float*)d_out;             // [B,T,D]
    float* wts = out + OUT_ELEMS;           // [B,H,T,T]

    void *pq, *pk, *pv, *pa;
    cudaGetSymbolAddress(&pq, g_qh);
    cudaGetSymbolAddress(&pk, g_kh);
    cudaGetSymbolAddress(&pv, g_vh);
    cudaGetSymbolAddress(&pa, g_att);
    float* qh  = (float*)pq;
    float* kh  = (float*)pk;
    float* vh  = (float*)pv;
    float* att = (float*)pa;

    dim3 blk(256);
    // Q/K/V projections in one launch (z selects)
    proj3_kernel<<<dim3(HD / 128, BT / 128, 3), blk>>>(q, k, v, Wq, Wk, Wv, qh, kh, vh);
    // Attention weights (writes the attn_weights output region)
    rbf_weights<<<dim3(Tt / 128, Tt / 128, Bb * Hh), blk>>>(qh, kh, wts);
    // attn = W @ V
    wv_gemm<<<dim3(Tt / 128, Bb * Hh), blk>>>(wts, vh, att);
    // out = attn @ Wo
    outproj_kernel<<<dim3(Dd / 128, BT / 128), blk>>>(att, Wo, out);
}